// round 14
// baseline (speedup 1.0000x reference)
#include <cuda_runtime.h>
#include <cuda_bf16.h>
#include <cuda_fp16.h>
#include <cstdint>
#include <math.h>

#define HDIM 64
#define KDIM 256
#define HW   65536
#define NPTS 262144
#define RATE_F 0.999f
#define EPS_F  1e-6f
#define PADF 257           // fp32 x-tile row pad (floats) -> conflict-free

typedef unsigned long long u64;
typedef unsigned int u32;

// Persistent device scratch (allocation-free rule).
__device__ __align__(16) float g_m  [KDIM * HDIM];   // codebook [k][c]
__device__ __align__(16) float g_mn [KDIM * HDIM];   // normalized [k][c] (out)
__device__ __align__(16) __half g_mnh[KDIM * HDIM];  // normalized fp16 [k][c] (assign)
__device__ __align__(16) float g_sum[KDIM * HDIM];
__device__ float g_cnt[KDIM];
__device__ float g_nrm[KDIM];

// ---- packed f32x2 helpers ----
__device__ __forceinline__ u64 pack2(float lo, float hi) {
    u64 r; asm("mov.b64 %0, {%1, %2};" : "=l"(r) : "f"(lo), "f"(hi)); return r;
}
__device__ __forceinline__ void unpack2(u64 v, float& lo, float& hi) {
    asm("mov.b64 {%0, %1}, %2;" : "=f"(lo), "=f"(hi) : "l"(v));
}
__device__ __forceinline__ void fma2(u64& d, u64 a, u64 b) {
    asm("fma.rn.f32x2 %0, %1, %2, %0;" : "+l"(d) : "l"(a), "l"(b));
}
__device__ __forceinline__ u64 add2(u64 a, u64 b) {
    u64 r; asm("add.rn.f32x2 %0, %1, %2;" : "=l"(r) : "l"(a), "l"(b)); return r;
}
__device__ __forceinline__ float ex2f(float x) {
    float r; asm("ex2.approx.f32 %0, %1;" : "=f"(r) : "f"(x)); return r;
}
__device__ __forceinline__ u32 h2(float hi, float lo) {       // {hi|lo} f16x2
    u32 r; asm("cvt.rn.f16x2.f32 %0, %1, %2;" : "=r"(r) : "f"(hi), "f"(lo)); return r;
}
__device__ __forceinline__ uint32_t smem_u32(const void* p) {
    uint32_t a;
    asm("{ .reg .u64 t; cvta.to.shared.u64 t, %1; cvt.u32.u64 %0, t; }" : "=r"(a) : "l"(p));
    return a;
}

// ---------------------------------------------------------------------------
// prep: m = units; mn = normalize(m); fp16 copy; nrm; zero sums.
// ---------------------------------------------------------------------------
__global__ void prep_kernel(const float* __restrict__ units) {
    int warp = threadIdx.x >> 5, lane = threadIdx.x & 31;
    int k = blockIdx.x * 8 + warp;
    if (k >= KDIM) return;
    float v0 = units[k * HDIM + lane];
    float v1 = units[k * HDIM + 32 + lane];
    g_m[k * HDIM + lane]      = v0;
    g_m[k * HDIM + 32 + lane] = v1;
    float ssq = v0 * v0 + v1 * v1;
    #pragma unroll
    for (int o = 16; o; o >>= 1) ssq += __shfl_xor_sync(0xFFFFFFFFu, ssq, o);
    float nrm = sqrtf(ssq);
    float inv = 1.0f / fmaxf(nrm, 1e-12f);
    float n0 = v0 * inv, n1 = v1 * inv;
    g_mn[k * HDIM + lane]      = n0;
    g_mn[k * HDIM + 32 + lane] = n1;
    g_mnh[k * HDIM + lane]      = __float2half(n0);
    g_mnh[k * HDIM + 32 + lane] = __float2half(n1);
    g_sum[k * HDIM + lane]      = 0.0f;
    g_sum[k * HDIM + 32 + lane] = 0.0f;
    if (lane == 0) { g_cnt[k] = 0.0f; g_nrm[k] = nrm; }
}

// ---------------------------------------------------------------------------
// assign via mma.sync fp16 (HMMA): CTA = 256 pts, 8 warps; warp = 32 pts x
// 256 k (K=64). fp16 (11-bit mantissa) cuts score error ~8x vs bf16 at the
// same MMA rate. A(x) frags one-time from fp32 smem; B(mn) via
// ldmatrix.x2.trans from 144B-stride fp16 tile. Running argmax, quad-reduce,
// warp-coop fp32 scatter. smem ~101 KB, 2 CTAs/SM.
// ---------------------------------------------------------------------------
#define S_XF   0                       // 64 * 257 * 4 = 65792
#define S_MN   65792                   // 256 * 144   = 36864
#define S_BK   102656                  // 256 * 4     = 1024
#define S_TOT  103680

__global__ void __launch_bounds__(256, 2) assign_kernel(const float* __restrict__ x) {
    extern __shared__ __align__(16) unsigned char smem[];
    float* sxf = (float*)(smem + S_XF);            // [64 c][257 pts]
    unsigned char* smn = smem + S_MN;              // [256 k][144 B] fp16 rows
    int*   sbk = (int*)(smem + S_BK);
    int tid = threadIdx.x;

    int hw0 = blockIdx.x * 256;
    int b   = hw0 >> 16;
    const float* xg = x + (size_t)b * HDIM * HW + (hw0 & (HW - 1));
    #pragma unroll 4
    for (int i = tid; i < HDIM * 256; i += 256) {
        int c = i >> 8, pt = i & 255;
        sxf[c * PADF + pt] = xg[(size_t)c * HW + pt];
    }
    {
        const uint4* src = (const uint4*)g_mnh;
        #pragma unroll 4
        for (int i = tid; i < KDIM * 8; i += 256) {
            int k = i >> 3, ch = i & 7;
            *(uint4*)(smn + k * 144 + ch * 16) = src[k * 8 + ch];
        }
    }
    __syncthreads();

    int w = tid >> 5, lane = tid & 31;
    int g = lane >> 2, q = lane & 3;
    int wBase = w * 32;

    // A fragments: A[t][jc][4], t = m-tile (16 pts), jc = k-chunk (16 c).
    u32 A[2][4][4];
    #pragma unroll
    for (int t = 0; t < 2; t++) {
        int p0 = wBase + 16 * t + g;
        int p1 = p0 + 8;
        #pragma unroll
        for (int jc = 0; jc < 4; jc++) {
            int c0 = 16 * jc + 2 * q;
            float a00 = sxf[(c0)     * PADF + p0], a01 = sxf[(c0 + 1) * PADF + p0];
            float a10 = sxf[(c0)     * PADF + p1], a11 = sxf[(c0 + 1) * PADF + p1];
            float a02 = sxf[(c0 + 8) * PADF + p0], a03 = sxf[(c0 + 9) * PADF + p0];
            float a12 = sxf[(c0 + 8) * PADF + p1], a13 = sxf[(c0 + 9) * PADF + p1];
            A[t][jc][0] = h2(a01, a00);
            A[t][jc][1] = h2(a11, a10);
            A[t][jc][2] = h2(a03, a02);
            A[t][jc][3] = h2(a13, a12);
        }
    }

    u32 mnS = smem_u32(smn);
    u32 rowAddr = mnS + (u32)((lane & 7) * 144) + ((lane & 8) ? 16u : 0u);

    float best[4] = {-1e30f, -1e30f, -1e30f, -1e30f};
    int   bkk[4]  = {0, 0, 0, 0};

    for (int n0 = 0; n0 < KDIM; n0 += 8) {
        float d0[4] = {0.f, 0.f, 0.f, 0.f};
        float d1[4] = {0.f, 0.f, 0.f, 0.f};
        #pragma unroll
        for (int jc = 0; jc < 4; jc++) {
            u32 b0, b1;
            asm volatile("ldmatrix.sync.aligned.m8n8.x2.trans.shared.b16 {%0,%1}, [%2];"
                         : "=r"(b0), "=r"(b1)
                         : "r"(rowAddr + (u32)(n0 * 144 + jc * 32)));
            asm volatile("mma.sync.aligned.m16n8k16.row.col.f32.f16.f16.f32 "
                         "{%0,%1,%2,%3}, {%4,%5,%6,%7}, {%8,%9}, {%0,%1,%2,%3};"
                         : "+f"(d0[0]), "+f"(d0[1]), "+f"(d0[2]), "+f"(d0[3])
                         : "r"(A[0][jc][0]), "r"(A[0][jc][1]), "r"(A[0][jc][2]), "r"(A[0][jc][3]),
                           "r"(b0), "r"(b1));
            asm volatile("mma.sync.aligned.m16n8k16.row.col.f32.f16.f16.f32 "
                         "{%0,%1,%2,%3}, {%4,%5,%6,%7}, {%8,%9}, {%0,%1,%2,%3};"
                         : "+f"(d1[0]), "+f"(d1[1]), "+f"(d1[2]), "+f"(d1[3])
                         : "r"(A[1][jc][0]), "r"(A[1][jc][1]), "r"(A[1][jc][2]), "r"(A[1][jc][3]),
                           "r"(b0), "r"(b1));
        }
        int k0 = n0 + 2 * q, k1 = k0 + 1;
        if (d0[0] > best[0]) { best[0] = d0[0]; bkk[0] = k0; }
        if (d0[1] > best[0]) { best[0] = d0[1]; bkk[0] = k1; }
        if (d0[2] > best[1]) { best[1] = d0[2]; bkk[1] = k0; }
        if (d0[3] > best[1]) { best[1] = d0[3]; bkk[1] = k1; }
        if (d1[0] > best[2]) { best[2] = d1[0]; bkk[2] = k0; }
        if (d1[1] > best[2]) { best[2] = d1[1]; bkk[2] = k1; }
        if (d1[2] > best[3]) { best[3] = d1[2]; bkk[3] = k0; }
        if (d1[3] > best[3]) { best[3] = d1[3]; bkk[3] = k1; }
    }

    #pragma unroll
    for (int r = 0; r < 4; r++) {
        #pragma unroll
        for (int o = 1; o <= 2; o <<= 1) {
            float ov = __shfl_xor_sync(0xFFFFFFFFu, best[r], o);
            int   ok = __shfl_xor_sync(0xFFFFFFFFu, bkk[r],  o);
            if (ov > best[r] || (ov == best[r] && ok < bkk[r])) { best[r] = ov; bkk[r] = ok; }
        }
    }
    if (q == 0) {
        sbk[wBase + g]      = bkk[0];
        sbk[wBase + g + 8]  = bkk[1];
        sbk[wBase + 16 + g] = bkk[2];
        sbk[wBase + 24 + g] = bkk[3];
    }
    __syncwarp();

    #pragma unroll 4
    for (int pl = 0; pl < 32; pl++) {
        int pt = wBase + pl;
        int bk = sbk[pt];
        float v0 = sxf[lane * PADF + pt];
        float v1 = sxf[(32 + lane) * PADF + pt];
        atomicAdd(g_sum + bk * HDIM + lane,      v0);
        atomicAdd(g_sum + bk * HDIM + 32 + lane, v1);
        if (lane == 0) atomicAdd(g_cnt + bk, 1.0f);
    }
}

// ---------------------------------------------------------------------------
// update3: closed-form 3-step EMA with frozen assignments.
// ---------------------------------------------------------------------------
__global__ void update3_kernel() {
    int warp = threadIdx.x >> 5, lane = threadIdx.x & 31;
    int k = blockIdx.x * 8 + warp;
    if (k >= KDIM) return;
    const float R3  = RATE_F * RATE_F * RATE_F;
    const float IR3 = 1.0f - R3;
    float sc = IR3 / (g_cnt[k] + EPS_F);
    float m0 = g_m[k * HDIM + lane]      * R3 + g_sum[k * HDIM + lane]      * sc;
    float m1 = g_m[k * HDIM + 32 + lane] * R3 + g_sum[k * HDIM + 32 + lane] * sc;
    g_m[k * HDIM + lane]      = m0;
    g_m[k * HDIM + 32 + lane] = m1;
    float ssq = m0 * m0 + m1 * m1;
    #pragma unroll
    for (int o = 16; o; o >>= 1) ssq += __shfl_xor_sync(0xFFFFFFFFu, ssq, o);
    float nrm = sqrtf(ssq);
    float inv = 1.0f / fmaxf(nrm, 1e-12f);
    g_mn[k * HDIM + lane]      = m0 * inv;
    g_mn[k * HDIM + 32 + lane] = m1 * inv;
    if (lane == 0) g_nrm[k] = nrm;
}

// ---------------------------------------------------------------------------
// out: 1 pt/thread, single softmax pass, xr pre-scaled by invn*log2e, bare
// ex2, m_k = mn_k*nrm_k. Dot now in 4 independent chains (serial latency
// 64 -> 32 cyc before ex2). 128-thr, 2 CTA/SM.
// ---------------------------------------------------------------------------
__global__ void __launch_bounds__(128, 2) out_kernel(const float* __restrict__ x,
                                                     float* __restrict__ out) {
    extern __shared__ ulonglong2 smem_raw[];
    ulonglong2* smq = smem_raw;                                  // mn: 4096 x 16B
    float* snrm = (float*)(smem_raw + KDIM * HDIM / 4);          // nrm: 256 floats
    const ulonglong2* gm = (const ulonglong2*)g_mn;
    #pragma unroll 8
    for (int i = threadIdx.x; i < KDIM * HDIM / 4; i += 128) smq[i] = gm[i];
    #pragma unroll 2
    for (int i = threadIdx.x; i < KDIM; i += 128) snrm[i] = g_nrm[i];
    __syncthreads();

    int p  = blockIdx.x * 128 + threadIdx.x;
    int b  = p >> 16;
    const float* xb = x + (size_t)b * HDIM * HW + (p & (HW - 1));

    float xf[HDIM];
    float s0 = 0.f, s1 = 0.f;
    #pragma unroll
    for (int i = 0; i < HDIM; i += 2) {
        float f0 = xb[(size_t)i * HW];
        float f1 = xb[(size_t)(i + 1) * HW];
        xf[i] = f0; xf[i + 1] = f1;
        s0 = fmaf(f0, f0, s0);
        s1 = fmaf(f1, f1, s1);
    }
    float scl = 1.44269504088896f / fmaxf(sqrtf(s0 + s1), 1e-12f);
    u64 xr[HDIM / 2];
    #pragma unroll
    for (int i = 0; i < HDIM / 2; i++)
        xr[i] = pack2(xf[2 * i] * scl, xf[2 * i + 1] * scl);

    u64 acc[HDIM / 2];
    #pragma unroll
    for (int i = 0; i < HDIM / 2; i++) acc[i] = 0ull;
    float den = 0.0f;

    for (int k = 0; k < KDIM; k++) {
        u64 v[HDIM / 2];
        const ulonglong2* row = smq + k * 16;
        #pragma unroll
        for (int i = 0; i < 16; i++) { ulonglong2 q = row[i]; v[2 * i] = q.x; v[2 * i + 1] = q.y; }
        u64 d0 = 0ull, d1 = 0ull, d2 = 0ull, d3 = 0ull;
        #pragma unroll
        for (int i = 0; i < 8; i++) {
            fma2(d0, xr[4 * i + 0], v[4 * i + 0]);
            fma2(d1, xr[4 * i + 1], v[4 * i + 1]);
            fma2(d2, xr[4 * i + 2], v[4 * i + 2]);
            fma2(d3, xr[4 * i + 3], v[4 * i + 3]);
        }
        float e0, e1;
        unpack2(add2(add2(d0, d1), add2(d2, d3)), e0, e1);
        float e = ex2f(e0 + e1);
        den += e;
        float wv = e * snrm[k];
        u64 w2 = pack2(wv, wv);
        #pragma unroll
        for (int i = 0; i < HDIM / 2; i++) fma2(acc[i], w2, v[i]);
    }

    float iden = 1.0f / den;
    float* ob = out + (size_t)b * HDIM * HW + (p & (HW - 1));
    #pragma unroll
    for (int i = 0; i < HDIM / 2; i++) {
        float f0, f1;
        unpack2(acc[i], f0, f1);
        ob[(size_t)(2 * i) * HW]     = f0 * iden;
        ob[(size_t)(2 * i + 1) * HW] = f1 * iden;
    }
}

// ---------------------------------------------------------------------------
extern "C" void kernel_launch(void* const* d_in, const int* in_sizes, int n_in,
                              void* d_out, int out_size) {
    const float* x;
    const float* units;
    if (in_sizes[0] >= in_sizes[1]) { x = (const float*)d_in[0]; units = (const float*)d_in[1]; }
    else                            { x = (const float*)d_in[1]; units = (const float*)d_in[0]; }
    float* out = (float*)d_out;

    const int out_bytes = (KDIM * HDIM + KDIM) * (int)sizeof(float);   // 65 KB
    cudaFuncSetAttribute(assign_kernel, cudaFuncAttributeMaxDynamicSharedMemorySize, S_TOT);
    cudaFuncSetAttribute(out_kernel,    cudaFuncAttributeMaxDynamicSharedMemorySize, out_bytes);

    prep_kernel<<<32, 256>>>(units);
    assign_kernel<<<NPTS / 256, 256, S_TOT>>>(x);
    update3_kernel<<<32, 256>>>();
    out_kernel<<<NPTS / 128, 128, out_bytes>>>(x, out);
}

// round 15
// speedup vs baseline: 1.0275x; 1.0275x over previous
#include <cuda_runtime.h>
#include <cuda_bf16.h>
#include <cuda_fp16.h>
#include <cstdint>
#include <math.h>

#define HDIM 64
#define KDIM 256
#define HW   65536
#define NPTS 262144
#define RATE_F 0.999f
#define EPS_F  1e-6f
#define PADF 257           // fp32 x-tile row pad (floats) -> conflict-free

typedef unsigned long long u64;
typedef unsigned int u32;

// Persistent device scratch (allocation-free rule).
__device__ __align__(16) float g_m  [KDIM * HDIM];   // codebook [k][c]
__device__ __align__(16) float g_mn [KDIM * HDIM];   // normalized [k][c] (out)
__device__ __align__(16) __half g_mnh[KDIM * HDIM];  // normalized fp16 [k][c] (assign)
__device__ __align__(16) float g_sum[KDIM * HDIM];
__device__ float g_cnt[KDIM];
__device__ float g_nrm[KDIM];

// ---- packed f32x2 helpers ----
__device__ __forceinline__ u64 pack2(float lo, float hi) {
    u64 r; asm("mov.b64 %0, {%1, %2};" : "=l"(r) : "f"(lo), "f"(hi)); return r;
}
__device__ __forceinline__ void unpack2(u64 v, float& lo, float& hi) {
    asm("mov.b64 {%0, %1}, %2;" : "=f"(lo), "=f"(hi) : "l"(v));
}
__device__ __forceinline__ void fma2(u64& d, u64 a, u64 b) {
    asm("fma.rn.f32x2 %0, %1, %2, %0;" : "+l"(d) : "l"(a), "l"(b));
}
__device__ __forceinline__ u64 add2(u64 a, u64 b) {
    u64 r; asm("add.rn.f32x2 %0, %1, %2;" : "=l"(r) : "l"(a), "l"(b)); return r;
}
__device__ __forceinline__ float ex2f(float x) {
    float r; asm("ex2.approx.f32 %0, %1;" : "=f"(r) : "f"(x)); return r;
}
__device__ __forceinline__ u32 h2(float hi, float lo) {       // dst = {hi|lo} f16x2
    u32 r; asm("cvt.rn.f16x2.f32 %0, %1, %2;" : "=r"(r) : "f"(hi), "f"(lo)); return r;
}

// ---------------------------------------------------------------------------
// prep: m = units; mn = normalize(m); fp16 copy; nrm; zero sums.
// ---------------------------------------------------------------------------
__global__ void prep_kernel(const float* __restrict__ units) {
    int warp = threadIdx.x >> 5, lane = threadIdx.x & 31;
    int k = blockIdx.x * 8 + warp;
    if (k >= KDIM) return;
    float v0 = units[k * HDIM + lane];
    float v1 = units[k * HDIM + 32 + lane];
    g_m[k * HDIM + lane]      = v0;
    g_m[k * HDIM + 32 + lane] = v1;
    float ssq = v0 * v0 + v1 * v1;
    #pragma unroll
    for (int o = 16; o; o >>= 1) ssq += __shfl_xor_sync(0xFFFFFFFFu, ssq, o);
    float nrm = sqrtf(ssq);
    float inv = 1.0f / fmaxf(nrm, 1e-12f);
    float n0 = v0 * inv, n1 = v1 * inv;
    g_mn[k * HDIM + lane]      = n0;
    g_mn[k * HDIM + 32 + lane] = n1;
    g_mnh[k * HDIM + lane]      = __float2half(n0);
    g_mnh[k * HDIM + 32 + lane] = __float2half(n1);
    g_sum[k * HDIM + lane]      = 0.0f;
    g_sum[k * HDIM + 32 + lane] = 0.0f;
    if (lane == 0) { g_cnt[k] = 0.0f; g_nrm[k] = nrm; }
}

// ---------------------------------------------------------------------------
// assign via mma.sync fp16 (HMMA), B fragments loaded by the DOCUMENTED
// PTX mapping (no ldmatrix): thread (g=lane>>2,q=lane&3) B reg0 =
// {B[2q][g],B[2q+1][g]} = 32-bit LDS of mn[n0+g][c0+2q..+1]; reg1 = c0+2q+8.
// CTA = 256 pts, 8 warps; warp = 32 pts x 256 k (K=64). Running argmax,
// quad-reduce (min-k ties), warp-coop fp32 scatter. smem ~101 KB, 2 CTAs/SM.
// ---------------------------------------------------------------------------
#define S_XF   0                       // 64 * 257 * 4 = 65792
#define S_MN   65792                   // 256 * 144   = 36864
#define S_BK   102656                  // 256 * 4     = 1024
#define S_TOT  103680

__global__ void __launch_bounds__(256, 2) assign_kernel(const float* __restrict__ x) {
    extern __shared__ __align__(16) unsigned char smem[];
    float* sxf = (float*)(smem + S_XF);            // [64 c][257 pts]
    unsigned char* smn = smem + S_MN;              // [256 k][144 B] fp16 rows
    int*   sbk = (int*)(smem + S_BK);
    int tid = threadIdx.x;

    int hw0 = blockIdx.x * 256;
    int b   = hw0 >> 16;
    const float* xg = x + (size_t)b * HDIM * HW + (hw0 & (HW - 1));
    #pragma unroll 4
    for (int i = tid; i < HDIM * 256; i += 256) {
        int c = i >> 8, pt = i & 255;
        sxf[c * PADF + pt] = xg[(size_t)c * HW + pt];
    }
    {
        const uint4* src = (const uint4*)g_mnh;
        #pragma unroll 4
        for (int i = tid; i < KDIM * 8; i += 256) {
            int k = i >> 3, ch = i & 7;
            *(uint4*)(smn + k * 144 + ch * 16) = src[k * 8 + ch];
        }
    }
    __syncthreads();

    int w = tid >> 5, lane = tid & 31;
    int g = lane >> 2, q = lane & 3;
    int wBase = w * 32;

    // A fragments per documented m16n8k16 layout:
    // reg0={A[g][2q],A[g][2q+1]} reg1={A[g+8][..]} reg2={A[g][2q+8..]} reg3={A[g+8][2q+8..]}
    u32 A[2][4][4];
    #pragma unroll
    for (int t = 0; t < 2; t++) {
        int p0 = wBase + 16 * t + g;
        int p1 = p0 + 8;
        #pragma unroll
        for (int jc = 0; jc < 4; jc++) {
            int c0 = 16 * jc + 2 * q;
            float a00 = sxf[(c0)     * PADF + p0], a01 = sxf[(c0 + 1) * PADF + p0];
            float a10 = sxf[(c0)     * PADF + p1], a11 = sxf[(c0 + 1) * PADF + p1];
            float a02 = sxf[(c0 + 8) * PADF + p0], a03 = sxf[(c0 + 9) * PADF + p0];
            float a12 = sxf[(c0 + 8) * PADF + p1], a13 = sxf[(c0 + 9) * PADF + p1];
            A[t][jc][0] = h2(a01, a00);
            A[t][jc][1] = h2(a11, a10);
            A[t][jc][2] = h2(a03, a02);
            A[t][jc][3] = h2(a13, a12);
        }
    }

    float best[4] = {-1e30f, -1e30f, -1e30f, -1e30f};
    int   bkk[4]  = {0, 0, 0, 0};

    for (int n0 = 0; n0 < KDIM; n0 += 8) {
        float d0[4] = {0.f, 0.f, 0.f, 0.f};
        float d1[4] = {0.f, 0.f, 0.f, 0.f};
        const unsigned char* brow = smn + (n0 + g) * 144;   // codebook entry n0+g
        #pragma unroll
        for (int jc = 0; jc < 4; jc++) {
            // B reg0 = {mn[n0+g][c0+2q], [c0+2q+1]}, reg1 = same +8 columns.
            u32 b0 = *(const u32*)(brow + (16 * jc + 2 * q) * 2);
            u32 b1 = *(const u32*)(brow + (16 * jc + 2 * q + 8) * 2);
            asm volatile("mma.sync.aligned.m16n8k16.row.col.f32.f16.f16.f32 "
                         "{%0,%1,%2,%3}, {%4,%5,%6,%7}, {%8,%9}, {%0,%1,%2,%3};"
                         : "+f"(d0[0]), "+f"(d0[1]), "+f"(d0[2]), "+f"(d0[3])
                         : "r"(A[0][jc][0]), "r"(A[0][jc][1]), "r"(A[0][jc][2]), "r"(A[0][jc][3]),
                           "r"(b0), "r"(b1));
            asm volatile("mma.sync.aligned.m16n8k16.row.col.f32.f16.f16.f32 "
                         "{%0,%1,%2,%3}, {%4,%5,%6,%7}, {%8,%9}, {%0,%1,%2,%3};"
                         : "+f"(d1[0]), "+f"(d1[1]), "+f"(d1[2]), "+f"(d1[3])
                         : "r"(A[1][jc][0]), "r"(A[1][jc][1]), "r"(A[1][jc][2]), "r"(A[1][jc][3]),
                           "r"(b0), "r"(b1));
        }
        // D fragment: d[0]=row g col 2q, d[1]=col 2q+1, d[2],d[3]=row g+8.
        int k0 = n0 + 2 * q, k1 = k0 + 1;
        if (d0[0] > best[0]) { best[0] = d0[0]; bkk[0] = k0; }
        if (d0[1] > best[0]) { best[0] = d0[1]; bkk[0] = k1; }
        if (d0[2] > best[1]) { best[1] = d0[2]; bkk[1] = k0; }
        if (d0[3] > best[1]) { best[1] = d0[3]; bkk[1] = k1; }
        if (d1[0] > best[2]) { best[2] = d1[0]; bkk[2] = k0; }
        if (d1[1] > best[2]) { best[2] = d1[1]; bkk[2] = k1; }
        if (d1[2] > best[3]) { best[3] = d1[2]; bkk[3] = k0; }
        if (d1[3] > best[3]) { best[3] = d1[3]; bkk[3] = k1; }
    }

    // Reduce across the 4 q-lanes sharing each row (xor 1, xor 2), min-k ties.
    #pragma unroll
    for (int r = 0; r < 4; r++) {
        #pragma unroll
        for (int o = 1; o <= 2; o <<= 1) {
            float ov = __shfl_xor_sync(0xFFFFFFFFu, best[r], o);
            int   ok = __shfl_xor_sync(0xFFFFFFFFu, bkk[r],  o);
            if (ov > best[r] || (ov == best[r] && ok < bkk[r])) { best[r] = ov; bkk[r] = ok; }
        }
    }
    if (q == 0) {
        sbk[wBase + g]      = bkk[0];   // rows g      (t=0)
        sbk[wBase + g + 8]  = bkk[1];   // rows g+8    (t=0)
        sbk[wBase + 16 + g] = bkk[2];   // rows g      (t=1)
        sbk[wBase + 24 + g] = bkk[3];   // rows g+8    (t=1)
    }
    __syncwarp();

    #pragma unroll 4
    for (int pl = 0; pl < 32; pl++) {
        int pt = wBase + pl;
        int bk = sbk[pt];
        float v0 = sxf[lane * PADF + pt];
        float v1 = sxf[(32 + lane) * PADF + pt];
        atomicAdd(g_sum + bk * HDIM + lane,      v0);
        atomicAdd(g_sum + bk * HDIM + 32 + lane, v1);
        if (lane == 0) atomicAdd(g_cnt + bk, 1.0f);
    }
}

// ---------------------------------------------------------------------------
// update3: closed-form 3-step EMA with frozen assignments.
// ---------------------------------------------------------------------------
__global__ void update3_kernel() {
    int warp = threadIdx.x >> 5, lane = threadIdx.x & 31;
    int k = blockIdx.x * 8 + warp;
    if (k >= KDIM) return;
    const float R3  = RATE_F * RATE_F * RATE_F;
    const float IR3 = 1.0f - R3;
    float sc = IR3 / (g_cnt[k] + EPS_F);
    float m0 = g_m[k * HDIM + lane]      * R3 + g_sum[k * HDIM + lane]      * sc;
    float m1 = g_m[k * HDIM + 32 + lane] * R3 + g_sum[k * HDIM + 32 + lane] * sc;
    g_m[k * HDIM + lane]      = m0;
    g_m[k * HDIM + 32 + lane] = m1;
    float ssq = m0 * m0 + m1 * m1;
    #pragma unroll
    for (int o = 16; o; o >>= 1) ssq += __shfl_xor_sync(0xFFFFFFFFu, ssq, o);
    float nrm = sqrtf(ssq);
    float inv = 1.0f / fmaxf(nrm, 1e-12f);
    g_mn[k * HDIM + lane]      = m0 * inv;
    g_mn[k * HDIM + 32 + lane] = m1 * inv;
    if (lane == 0) g_nrm[k] = nrm;
}

// ---------------------------------------------------------------------------
// out (R13/R11 form — best measured): 1 pt/thread, single softmax pass, xr
// pre-scaled by invn*log2e, bare ex2, m_k = mn_k*nrm_k. 128-thr, 2 CTA/SM.
// ---------------------------------------------------------------------------
__global__ void __launch_bounds__(128, 2) out_kernel(const float* __restrict__ x,
                                                     float* __restrict__ out) {
    extern __shared__ ulonglong2 smem_raw[];
    ulonglong2* smq = smem_raw;                                  // mn: 4096 x 16B
    float* snrm = (float*)(smem_raw + KDIM * HDIM / 4);          // nrm: 256 floats
    const ulonglong2* gm = (const ulonglong2*)g_mn;
    #pragma unroll 8
    for (int i = threadIdx.x; i < KDIM * HDIM / 4; i += 128) smq[i] = gm[i];
    #pragma unroll 2
    for (int i = threadIdx.x; i < KDIM; i += 128) snrm[i] = g_nrm[i];
    __syncthreads();

    int p  = blockIdx.x * 128 + threadIdx.x;
    int b  = p >> 16;
    const float* xb = x + (size_t)b * HDIM * HW + (p & (HW - 1));

    float xf[HDIM];
    float s0 = 0.f, s1 = 0.f;
    #pragma unroll
    for (int i = 0; i < HDIM; i += 2) {
        float f0 = xb[(size_t)i * HW];
        float f1 = xb[(size_t)(i + 1) * HW];
        xf[i] = f0; xf[i + 1] = f1;
        s0 = fmaf(f0, f0, s0);
        s1 = fmaf(f1, f1, s1);
    }
    float scl = 1.44269504088896f / fmaxf(sqrtf(s0 + s1), 1e-12f);
    u64 xr[HDIM / 2];
    #pragma unroll
    for (int i = 0; i < HDIM / 2; i++)
        xr[i] = pack2(xf[2 * i] * scl, xf[2 * i + 1] * scl);

    u64 acc[HDIM / 2];
    #pragma unroll
    for (int i = 0; i < HDIM / 2; i++) acc[i] = 0ull;
    float den = 0.0f;

    for (int k = 0; k < KDIM; k++) {
        u64 v[HDIM / 2];
        const ulonglong2* row = smq + k * 16;
        #pragma unroll
        for (int i = 0; i < 16; i++) { ulonglong2 q = row[i]; v[2 * i] = q.x; v[2 * i + 1] = q.y; }
        u64 d0 = 0ull, d1 = 0ull;
        #pragma unroll
        for (int i = 0; i < 16; i++) {
            fma2(d0, xr[2 * i],     v[2 * i]);
            fma2(d1, xr[2 * i + 1], v[2 * i + 1]);
        }
        float e0, e1;
        unpack2(add2(d0, d1), e0, e1);
        float e = ex2f(e0 + e1);
        den += e;
        float wv = e * snrm[k];
        u64 w2 = pack2(wv, wv);
        #pragma unroll
        for (int i = 0; i < HDIM / 2; i++) fma2(acc[i], w2, v[i]);
    }

    float iden = 1.0f / den;
    float* ob = out + (size_t)b * HDIM * HW + (p & (HW - 1));
    #pragma unroll
    for (int i = 0; i < HDIM / 2; i++) {
        float f0, f1;
        unpack2(acc[i], f0, f1);
        ob[(size_t)(2 * i) * HW]     = f0 * iden;
        ob[(size_t)(2 * i + 1) * HW] = f1 * iden;
    }
}

// ---------------------------------------------------------------------------
extern "C" void kernel_launch(void* const* d_in, const int* in_sizes, int n_in,
                              void* d_out, int out_size) {
    const float* x;
    const float* units;
    if (in_sizes[0] >= in_sizes[1]) { x = (const float*)d_in[0]; units = (const float*)d_in[1]; }
    else                            { x = (const float*)d_in[1]; units = (const float*)d_in[0]; }
    float* out = (float*)d_out;

    const int out_bytes = (KDIM * HDIM + KDIM) * (int)sizeof(float);   // 65 KB
    cudaFuncSetAttribute(assign_kernel, cudaFuncAttributeMaxDynamicSharedMemorySize, S_TOT);
    cudaFuncSetAttribute(out_kernel,    cudaFuncAttributeMaxDynamicSharedMemorySize, out_bytes);

    prep_kernel<<<32, 256>>>(units);
    assign_kernel<<<NPTS / 256, 256, S_TOT>>>(x);
    update3_kernel<<<32, 256>>>();
    out_kernel<<<NPTS / 128, 128, out_bytes>>>(x, out);
}

// round 16
// speedup vs baseline: 2.1720x; 2.1139x over previous
#include <cuda_runtime.h>
#include <cuda_bf16.h>
#include <cuda_fp16.h>
#include <cstdint>
#include <math.h>

#define HDIM 64
#define KDIM 256
#define HW   65536
#define NPTS 262144
#define RATE_F 0.999f
#define EPS_F  1e-6f
#define PADF 257           // fp32 x-tile row pad (floats) -> conflict-free

typedef unsigned long long u64;
typedef unsigned int u32;

// Persistent device scratch (allocation-free rule).
__device__ __align__(16) float g_m  [KDIM * HDIM];   // codebook EMA state [k][c]
__device__ __align__(16) __half g_mnh[KDIM * HDIM];  // normalized fp16 [k][c] (GEMM B)
__device__ __align__(16) __half g_mTh[HDIM * KDIM];  // m transposed fp16 hi [c][k]
__device__ __align__(16) __half g_mTl[HDIM * KDIM];  // m transposed fp16 lo [c][k]
__device__ __align__(16) float g_sum[KDIM * HDIM];
__device__ float g_cnt[KDIM];

__device__ __forceinline__ float ex2f(float x) {
    float r; asm("ex2.approx.f32 %0, %1;" : "=f"(r) : "f"(x)); return r;
}
__device__ __forceinline__ u32 h2(float hi, float lo) {       // dst = {hi|lo} f16x2
    u32 r; asm("cvt.rn.f16x2.f32 %0, %1, %2;" : "=r"(r) : "f"(hi), "f"(lo)); return r;
}

#define MMA16816(D, A, B0, B1)                                               \
    asm volatile("mma.sync.aligned.m16n8k16.row.col.f32.f16.f16.f32 "        \
                 "{%0,%1,%2,%3}, {%4,%5,%6,%7}, {%8,%9}, {%0,%1,%2,%3};"     \
                 : "+f"((D)[0]), "+f"((D)[1]), "+f"((D)[2]), "+f"((D)[3])    \
                 : "r"((A)[0]), "r"((A)[1]), "r"((A)[2]), "r"((A)[3]),       \
                   "r"(B0), "r"(B1))

// ---------------------------------------------------------------------------
// prep: m = units; g_mnh = fp16(normalize(m)); zero sums/counts.
// ---------------------------------------------------------------------------
__global__ void prep_kernel(const float* __restrict__ units) {
    int warp = threadIdx.x >> 5, lane = threadIdx.x & 31;
    int k = blockIdx.x * 8 + warp;
    if (k >= KDIM) return;
    float v0 = units[k * HDIM + lane];
    float v1 = units[k * HDIM + 32 + lane];
    g_m[k * HDIM + lane]      = v0;
    g_m[k * HDIM + 32 + lane] = v1;
    float ssq = v0 * v0 + v1 * v1;
    #pragma unroll
    for (int o = 16; o; o >>= 1) ssq += __shfl_xor_sync(0xFFFFFFFFu, ssq, o);
    float inv = 1.0f / fmaxf(sqrtf(ssq), 1e-12f);
    g_mnh[k * HDIM + lane]      = __float2half(v0 * inv);
    g_mnh[k * HDIM + 32 + lane] = __float2half(v1 * inv);
    g_sum[k * HDIM + lane]      = 0.0f;
    g_sum[k * HDIM + 32 + lane] = 0.0f;
    if (lane == 0) g_cnt[k] = 0.0f;
}

// ---------------------------------------------------------------------------
// assign via mma.sync fp16 (validated R15): CTA = 256 pts, 8 warps; warp =
// 32 pts x 256 k (K=64). B frags by documented PTX mapping (direct LDS).
// Running argmax, quad-reduce (min-k ties), warp-coop fp32 scatter.
// ---------------------------------------------------------------------------
#define S_XF   0                       // 64 * 257 * 4 = 65792
#define S_MN   65792                   // 256 * 144   = 36864
#define S_BK   102656                  // 256 * 4     = 1024
#define S_TOT  103680

__global__ void __launch_bounds__(256, 2) assign_kernel(const float* __restrict__ x) {
    extern __shared__ __align__(16) unsigned char smem[];
    float* sxf = (float*)(smem + S_XF);            // [64 c][257 pts]
    unsigned char* smn = smem + S_MN;              // [256 k][144 B] fp16 rows
    int*   sbk = (int*)(smem + S_BK);
    int tid = threadIdx.x;

    int hw0 = blockIdx.x * 256;
    int b   = hw0 >> 16;
    const float* xg = x + (size_t)b * HDIM * HW + (hw0 & (HW - 1));
    #pragma unroll 4
    for (int i = tid; i < HDIM * 256; i += 256) {
        int c = i >> 8, pt = i & 255;
        sxf[c * PADF + pt] = xg[(size_t)c * HW + pt];
    }
    {
        const uint4* src = (const uint4*)g_mnh;
        #pragma unroll 4
        for (int i = tid; i < KDIM * 8; i += 256) {
            int k = i >> 3, ch = i & 7;
            *(uint4*)(smn + k * 144 + ch * 16) = src[k * 8 + ch];
        }
    }
    __syncthreads();

    int w = tid >> 5, lane = tid & 31;
    int g = lane >> 2, q = lane & 3;
    int wBase = w * 32;

    u32 A[2][4][4];
    #pragma unroll
    for (int t = 0; t < 2; t++) {
        int p0 = wBase + 16 * t + g;
        int p1 = p0 + 8;
        #pragma unroll
        for (int jc = 0; jc < 4; jc++) {
            int c0 = 16 * jc + 2 * q;
            float a00 = sxf[(c0)     * PADF + p0], a01 = sxf[(c0 + 1) * PADF + p0];
            float a10 = sxf[(c0)     * PADF + p1], a11 = sxf[(c0 + 1) * PADF + p1];
            float a02 = sxf[(c0 + 8) * PADF + p0], a03 = sxf[(c0 + 9) * PADF + p0];
            float a12 = sxf[(c0 + 8) * PADF + p1], a13 = sxf[(c0 + 9) * PADF + p1];
            A[t][jc][0] = h2(a01, a00);
            A[t][jc][1] = h2(a11, a10);
            A[t][jc][2] = h2(a03, a02);
            A[t][jc][3] = h2(a13, a12);
        }
    }

    float best[4] = {-1e30f, -1e30f, -1e30f, -1e30f};
    int   bkk[4]  = {0, 0, 0, 0};

    for (int n0 = 0; n0 < KDIM; n0 += 8) {
        float d0[4] = {0.f, 0.f, 0.f, 0.f};
        float d1[4] = {0.f, 0.f, 0.f, 0.f};
        const unsigned char* brow = smn + (n0 + g) * 144;
        #pragma unroll
        for (int jc = 0; jc < 4; jc++) {
            u32 b0 = *(const u32*)(brow + (16 * jc + 2 * q) * 2);
            u32 b1 = *(const u32*)(brow + (16 * jc + 2 * q + 8) * 2);
            MMA16816(d0, A[0][jc], b0, b1);
            MMA16816(d1, A[1][jc], b0, b1);
        }
        int k0 = n0 + 2 * q, k1 = k0 + 1;
        if (d0[0] > best[0]) { best[0] = d0[0]; bkk[0] = k0; }
        if (d0[1] > best[0]) { best[0] = d0[1]; bkk[0] = k1; }
        if (d0[2] > best[1]) { best[1] = d0[2]; bkk[1] = k0; }
        if (d0[3] > best[1]) { best[1] = d0[3]; bkk[1] = k1; }
        if (d1[0] > best[2]) { best[2] = d1[0]; bkk[2] = k0; }
        if (d1[1] > best[2]) { best[2] = d1[1]; bkk[2] = k1; }
        if (d1[2] > best[3]) { best[3] = d1[2]; bkk[3] = k0; }
        if (d1[3] > best[3]) { best[3] = d1[3]; bkk[3] = k1; }
    }

    #pragma unroll
    for (int r = 0; r < 4; r++) {
        #pragma unroll
        for (int o = 1; o <= 2; o <<= 1) {
            float ov = __shfl_xor_sync(0xFFFFFFFFu, best[r], o);
            int   ok = __shfl_xor_sync(0xFFFFFFFFu, bkk[r],  o);
            if (ov > best[r] || (ov == best[r] && ok < bkk[r])) { best[r] = ov; bkk[r] = ok; }
        }
    }
    if (q == 0) {
        sbk[wBase + g]      = bkk[0];
        sbk[wBase + g + 8]  = bkk[1];
        sbk[wBase + 16 + g] = bkk[2];
        sbk[wBase + 24 + g] = bkk[3];
    }
    __syncwarp();

    #pragma unroll 4
    for (int pl = 0; pl < 32; pl++) {
        int pt = wBase + pl;
        int bk = sbk[pt];
        float v0 = sxf[lane * PADF + pt];
        float v1 = sxf[(32 + lane) * PADF + pt];
        atomicAdd(g_sum + bk * HDIM + lane,      v0);
        atomicAdd(g_sum + bk * HDIM + 32 + lane, v1);
        if (lane == 0) atomicAdd(g_cnt + bk, 1.0f);
    }
}

// ---------------------------------------------------------------------------
// update3: closed-form 3-step EMA with frozen assignments; emit fp16 mn
// (GEMM1 B of out) and fp16 hi/lo transposed m (GEMM2 B of out).
// ---------------------------------------------------------------------------
__global__ void update3_kernel() {
    int warp = threadIdx.x >> 5, lane = threadIdx.x & 31;
    int k = blockIdx.x * 8 + warp;
    if (k >= KDIM) return;
    const float R3  = RATE_F * RATE_F * RATE_F;
    const float IR3 = 1.0f - R3;
    float sc = IR3 / (g_cnt[k] + EPS_F);
    float m0 = g_m[k * HDIM + lane]      * R3 + g_sum[k * HDIM + lane]      * sc;
    float m1 = g_m[k * HDIM + 32 + lane] * R3 + g_sum[k * HDIM + 32 + lane] * sc;
    g_m[k * HDIM + lane]      = m0;
    g_m[k * HDIM + 32 + lane] = m1;
    float ssq = m0 * m0 + m1 * m1;
    #pragma unroll
    for (int o = 16; o; o >>= 1) ssq += __shfl_xor_sync(0xFFFFFFFFu, ssq, o);
    float inv = 1.0f / fmaxf(sqrtf(ssq), 1e-12f);
    g_mnh[k * HDIM + lane]      = __float2half(m0 * inv);
    g_mnh[k * HDIM + 32 + lane] = __float2half(m1 * inv);
    // transposed hi/lo split of m
    __half h0 = __float2half(m0);
    __half h1 = __float2half(m1);
    g_mTh[lane * KDIM + k]        = h0;
    g_mTh[(32 + lane) * KDIM + k] = h1;
    g_mTl[lane * KDIM + k]        = __float2half(m0 - __half2float(h0));
    g_mTl[(32 + lane) * KDIM + k] = __float2half(m1 - __half2float(h1));
}

// ---------------------------------------------------------------------------
// out via HMMA (flash-attention style):
//   GEMM1: S = Xscl(fp16) . MN(fp16)^T  (scores in log2 domain; abs err ~5e-5)
//   e = ex2(S); den += e  (fragment-local; D-layout == A-layout of GEMM2)
//   GEMM2: N += e_hi.mT_hi + e_hi.mT_lo + e_lo.mT_hi   (3-term, err ~2^-22)
//   out = N / den.
// CTA = 256 pts, 8 warps (warp = 32 pts), k in 4 blocks of 64, t-tiles
// sequential to bound registers. smem 138 KB, 1 CTA/SM.
// ---------------------------------------------------------------------------
#define O_XH   0                       // [256 pt][72 h] = 36864
#define O_MN   36864                   // [256 k][144 B] = 36864
#define O_MTH  73728                   // [64 c][264 h]  = 33792
#define O_MTL  107520                  // [64 c][264 h]  = 33792
#define O_TOT  141312

__global__ void __launch_bounds__(256, 1) out_kernel(const float* __restrict__ x,
                                                     float* __restrict__ out) {
    extern __shared__ __align__(16) unsigned char smem[];
    __half* sxh = (__half*)(smem + O_XH);          // [pt][72h] rows 144B
    unsigned char* smn = smem + O_MN;              // [k][144B]
    __half* smtH = (__half*)(smem + O_MTH);        // [c][264h] rows 528B
    __half* smtL = (__half*)(smem + O_MTL);
    int tid = threadIdx.x;

    {
        const uint4* src = (const uint4*)g_mnh;
        #pragma unroll 4
        for (int i = tid; i < KDIM * 8; i += 256) {
            int k = i >> 3, ch = i & 7;
            *(uint4*)(smn + k * 144 + ch * 16) = src[k * 8 + ch];
        }
        const uint4* sh = (const uint4*)g_mTh;
        const uint4* sl = (const uint4*)g_mTl;
        #pragma unroll 4
        for (int i = tid; i < 64 * 32; i += 256) {
            int c = i >> 5, ch = i & 31;
            *(uint4*)((unsigned char*)smtH + c * 528 + ch * 16) = sh[i];
            *(uint4*)((unsigned char*)smtL + c * 528 + ch * 16) = sl[i];
        }
    }
    // x: thread = point. Coalesced gmem loads; fp16(x * invn * log2e) -> smem.
    int hw0 = blockIdx.x * 256;
    int b   = hw0 >> 16;
    const float* xb = x + (size_t)b * HDIM * HW + (hw0 & (HW - 1)) + tid;
    float xf[HDIM];
    float s0 = 0.f, s1 = 0.f;
    #pragma unroll
    for (int c = 0; c < HDIM; c += 2) {
        float f0 = xb[(size_t)c * HW];
        float f1 = xb[(size_t)(c + 1) * HW];
        xf[c] = f0; xf[c + 1] = f1;
        s0 = fmaf(f0, f0, s0);
        s1 = fmaf(f1, f1, s1);
    }
    float scl = 1.44269504088896f / fmaxf(sqrtf(s0 + s1), 1e-12f);
    {
        __half* myrow = sxh + tid * 72;
        #pragma unroll
        for (int c = 0; c < HDIM; c++) myrow[c] = __float2half(xf[c] * scl);
    }
    __syncthreads();

    int w = tid >> 5, lane = tid & 31;
    int g = lane >> 2, q = lane & 3;
    int wBase = w * 32;

    // GEMM1 A fragments (x, fp16) — persistent.
    u32 A1[2][4][4];
    #pragma unroll
    for (int t = 0; t < 2; t++) {
        const __half* r0 = sxh + (wBase + 16 * t + g) * 72;
        const __half* r1 = r0 + 8 * 72;
        #pragma unroll
        for (int jc = 0; jc < 4; jc++) {
            int c0 = 16 * jc + 2 * q;
            A1[t][jc][0] = *(const u32*)(r0 + c0);
            A1[t][jc][1] = *(const u32*)(r1 + c0);
            A1[t][jc][2] = *(const u32*)(r0 + c0 + 8);
            A1[t][jc][3] = *(const u32*)(r1 + c0 + 8);
        }
    }

    float acc[2][8][4];
    #pragma unroll
    for (int t = 0; t < 2; t++)
        #pragma unroll
        for (int ct = 0; ct < 8; ct++)
            #pragma unroll
            for (int v = 0; v < 4; v++) acc[t][ct][v] = 0.0f;
    float den[4] = {0.f, 0.f, 0.f, 0.f};

    #pragma unroll
    for (int kb = 0; kb < 4; kb++) {
        #pragma unroll
        for (int t = 0; t < 2; t++) {
            // --- GEMM1: scores for 64 codes (log2 domain) ---
            float s[8][4];
            #pragma unroll
            for (int i = 0; i < 8; i++)
                #pragma unroll
                for (int v = 0; v < 4; v++) s[i][v] = 0.0f;
            #pragma unroll
            for (int i = 0; i < 8; i++) {
                const unsigned char* brow = smn + (kb * 64 + 8 * i + g) * 144;
                #pragma unroll
                for (int jc = 0; jc < 4; jc++) {
                    u32 b0 = *(const u32*)(brow + (16 * jc + 2 * q) * 2);
                    u32 b1 = *(const u32*)(brow + (16 * jc + 2 * q + 8) * 2);
                    MMA16816(s[i], A1[t][jc], b0, b1);
                }
            }
            // --- e = 2^s; den accumulation (v<2: row g, v>=2: row g+8) ---
            #pragma unroll
            for (int i = 0; i < 8; i++) {
                #pragma unroll
                for (int v = 0; v < 4; v++) {
                    float e = ex2f(s[i][v]);
                    s[i][v] = e;
                    den[2 * t + (v >> 1)] += e;
                }
            }
            // --- e -> GEMM2 A fragments (hi/lo split, zero data movement) ---
            u32 AH[4][4], AL[4][4];
            #pragma unroll
            for (int j = 0; j < 4; j++) {
                #pragma unroll
                for (int r = 0; r < 4; r++) {
                    int i = 2 * j + (r >> 1);       // r=0,1: i=2j; r=2,3: i=2j+1
                    int v = (r & 1) * 2;            // r even: vals 0,1; odd: 2,3
                    float w0 = s[i][v], w1 = s[i][v + 1];
                    u32 hi = h2(w1, w0);
                    float2 hf = __half22float2(*(__half2*)&hi);
                    AH[j][r] = hi;
                    AL[j][r] = h2(w1 - hf.y, w0 - hf.x);
                }
            }
            // Reorder AH/AL rows to A-frag convention: reg order is
            // {row g k-lo, row g+8 k-lo, row g k-hi, row g+8 k-hi}:
            // built above as r: 0=(i=2j,rows g),1=(i=2j,rows g+8),
            //                 2=(i=2j+1,rows g),3=(i=2j+1,rows g+8)  — matches:
            // reg0 = r0 (g, cols 2q), reg1 = r1 (g+8), reg2 = r2 (g, +8 cols),
            // reg3 = r3. (i=2j -> k offset 0..7; i=2j+1 -> k offset 8..15.)
            // --- GEMM2: acc += e * mT ---
            #pragma unroll
            for (int ct = 0; ct < 8; ct++) {
                const __half* rH = smtH + (8 * ct + g) * 264;
                const __half* rL = smtL + (8 * ct + g) * 264;
                #pragma unroll
                for (int j = 0; j < 4; j++) {
                    int koff = kb * 64 + 16 * j + 2 * q;
                    u32 b0h = *(const u32*)(rH + koff);
                    u32 b1h = *(const u32*)(rH + koff + 8);
                    u32 b0l = *(const u32*)(rL + koff);
                    u32 b1l = *(const u32*)(rL + koff + 8);
                    MMA16816(acc[t][ct], AH[j], b0h, b1h);
                    MMA16816(acc[t][ct], AH[j], b0l, b1l);
                    MMA16816(acc[t][ct], AL[j], b0h, b1h);
                }
            }
        }
    }

    // den: sum across the 4 q-lanes sharing each row.
    #pragma unroll
    for (int r = 0; r < 4; r++) {
        den[r] += __shfl_xor_sync(0xFFFFFFFFu, den[r], 1);
        den[r] += __shfl_xor_sync(0xFFFFFFFFu, den[r], 2);
    }
    float iden[4];
    #pragma unroll
    for (int r = 0; r < 4; r++) iden[r] = 1.0f / den[r];

    int hwb = hw0 & (HW - 1);
    float* ob = out + (size_t)b * HDIM * HW + hwb;
    #pragma unroll
    for (int t = 0; t < 2; t++) {
        #pragma unroll
        for (int ct = 0; ct < 8; ct++) {
            int c  = 8 * ct + 2 * q;
            int p0 = wBase + 16 * t + g;
            ob[(size_t)c * HW + p0]           = acc[t][ct][0] * iden[2 * t];
            ob[(size_t)(c + 1) * HW + p0]     = acc[t][ct][1] * iden[2 * t];
            ob[(size_t)c * HW + p0 + 8]       = acc[t][ct][2] * iden[2 * t + 1];
            ob[(size_t)(c + 1) * HW + p0 + 8] = acc[t][ct][3] * iden[2 * t + 1];
        }
    }
}

// ---------------------------------------------------------------------------
extern "C" void kernel_launch(void* const* d_in, const int* in_sizes, int n_in,
                              void* d_out, int out_size) {
    const float* x;
    const float* units;
    if (in_sizes[0] >= in_sizes[1]) { x = (const float*)d_in[0]; units = (const float*)d_in[1]; }
    else                            { x = (const float*)d_in[1]; units = (const float*)d_in[0]; }
    float* out = (float*)d_out;

    cudaFuncSetAttribute(assign_kernel, cudaFuncAttributeMaxDynamicSharedMemorySize, S_TOT);
    cudaFuncSetAttribute(out_kernel,    cudaFuncAttributeMaxDynamicSharedMemorySize, O_TOT);

    prep_kernel<<<32, 256>>>(units);
    assign_kernel<<<NPTS / 256, 256, S_TOT>>>(x);
    update3_kernel<<<32, 256>>>();
    out_kernel<<<NPTS / 256, 256, O_TOT>>>(x, out);
}

// round 17
// speedup vs baseline: 2.4620x; 1.1335x over previous
#include <cuda_runtime.h>
#include <cuda_bf16.h>
#include <cuda_fp16.h>
#include <cstdint>
#include <math.h>

#define HDIM 64
#define KDIM 256
#define HW   65536
#define NPTS 262144
#define RATE_F 0.999f
#define EPS_F  1e-6f
#define PADF 257           // fp32 x-tile row pad (floats) -> conflict-free

typedef unsigned long long u64;
typedef unsigned int u32;

// Persistent device scratch (allocation-free rule).
__device__ __align__(16) float g_m  [KDIM * HDIM];   // codebook EMA state [k][c]
__device__ __align__(16) __half g_mnh[KDIM * HDIM];  // normalized fp16 [k][c] (GEMM B)
__device__ __align__(16) __half g_mTh[HDIM * KDIM];  // m transposed fp16 [c][k]
__device__ __align__(16) float g_sum[KDIM * HDIM];
__device__ float g_cnt[KDIM];

__device__ __forceinline__ float ex2f(float x) {
    float r; asm("ex2.approx.f32 %0, %1;" : "=f"(r) : "f"(x)); return r;
}
__device__ __forceinline__ u32 h2(float hi, float lo) {       // dst = {hi|lo} f16x2
    u32 r; asm("cvt.rn.f16x2.f32 %0, %1, %2;" : "=r"(r) : "f"(hi), "f"(lo)); return r;
}

#define MMA16816(D, A, B0, B1)                                               \
    asm volatile("mma.sync.aligned.m16n8k16.row.col.f32.f16.f16.f32 "        \
                 "{%0,%1,%2,%3}, {%4,%5,%6,%7}, {%8,%9}, {%0,%1,%2,%3};"     \
                 : "+f"((D)[0]), "+f"((D)[1]), "+f"((D)[2]), "+f"((D)[3])    \
                 : "r"((A)[0]), "r"((A)[1]), "r"((A)[2]), "r"((A)[3]),       \
                   "r"(B0), "r"(B1))

// ---------------------------------------------------------------------------
// prep: m = units; g_mnh = fp16(normalize(m)); zero sums/counts.
// ---------------------------------------------------------------------------
__global__ void prep_kernel(const float* __restrict__ units) {
    int warp = threadIdx.x >> 5, lane = threadIdx.x & 31;
    int k = blockIdx.x * 8 + warp;
    if (k >= KDIM) return;
    float v0 = units[k * HDIM + lane];
    float v1 = units[k * HDIM + 32 + lane];
    g_m[k * HDIM + lane]      = v0;
    g_m[k * HDIM + 32 + lane] = v1;
    float ssq = v0 * v0 + v1 * v1;
    #pragma unroll
    for (int o = 16; o; o >>= 1) ssq += __shfl_xor_sync(0xFFFFFFFFu, ssq, o);
    float inv = 1.0f / fmaxf(sqrtf(ssq), 1e-12f);
    g_mnh[k * HDIM + lane]      = __float2half(v0 * inv);
    g_mnh[k * HDIM + 32 + lane] = __float2half(v1 * inv);
    g_sum[k * HDIM + lane]      = 0.0f;
    g_sum[k * HDIM + 32 + lane] = 0.0f;
    if (lane == 0) g_cnt[k] = 0.0f;
}

// ---------------------------------------------------------------------------
// assign via mma.sync fp16 (validated R15/R16): CTA = 256 pts, 8 warps; warp
// = 32 pts x 256 k (K=64). B frags by documented PTX mapping (direct LDS).
// Running argmax, quad-reduce (min-k ties), warp-coop fp32 scatter.
// ---------------------------------------------------------------------------
#define S_XF   0                       // 64 * 257 * 4 = 65792
#define S_MN   65792                   // 256 * 144   = 36864
#define S_BK   102656                  // 256 * 4     = 1024
#define S_TOT  103680

__global__ void __launch_bounds__(256, 2) assign_kernel(const float* __restrict__ x) {
    extern __shared__ __align__(16) unsigned char smem[];
    float* sxf = (float*)(smem + S_XF);            // [64 c][257 pts]
    unsigned char* smn = smem + S_MN;              // [256 k][144 B] fp16 rows
    int*   sbk = (int*)(smem + S_BK);
    int tid = threadIdx.x;

    int hw0 = blockIdx.x * 256;
    int b   = hw0 >> 16;
    const float* xg = x + (size_t)b * HDIM * HW + (hw0 & (HW - 1));
    #pragma unroll 4
    for (int i = tid; i < HDIM * 256; i += 256) {
        int c = i >> 8, pt = i & 255;
        sxf[c * PADF + pt] = xg[(size_t)c * HW + pt];
    }
    {
        const uint4* src = (const uint4*)g_mnh;
        #pragma unroll 4
        for (int i = tid; i < KDIM * 8; i += 256) {
            int k = i >> 3, ch = i & 7;
            *(uint4*)(smn + k * 144 + ch * 16) = src[k * 8 + ch];
        }
    }
    __syncthreads();

    int w = tid >> 5, lane = tid & 31;
    int g = lane >> 2, q = lane & 3;
    int wBase = w * 32;

    u32 A[2][4][4];
    #pragma unroll
    for (int t = 0; t < 2; t++) {
        int p0 = wBase + 16 * t + g;
        int p1 = p0 + 8;
        #pragma unroll
        for (int jc = 0; jc < 4; jc++) {
            int c0 = 16 * jc + 2 * q;
            float a00 = sxf[(c0)     * PADF + p0], a01 = sxf[(c0 + 1) * PADF + p0];
            float a10 = sxf[(c0)     * PADF + p1], a11 = sxf[(c0 + 1) * PADF + p1];
            float a02 = sxf[(c0 + 8) * PADF + p0], a03 = sxf[(c0 + 9) * PADF + p0];
            float a12 = sxf[(c0 + 8) * PADF + p1], a13 = sxf[(c0 + 9) * PADF + p1];
            A[t][jc][0] = h2(a01, a00);
            A[t][jc][1] = h2(a11, a10);
            A[t][jc][2] = h2(a03, a02);
            A[t][jc][3] = h2(a13, a12);
        }
    }

    float best[4] = {-1e30f, -1e30f, -1e30f, -1e30f};
    int   bkk[4]  = {0, 0, 0, 0};

    for (int n0 = 0; n0 < KDIM; n0 += 8) {
        float d0[4] = {0.f, 0.f, 0.f, 0.f};
        float d1[4] = {0.f, 0.f, 0.f, 0.f};
        const unsigned char* brow = smn + (n0 + g) * 144;
        #pragma unroll
        for (int jc = 0; jc < 4; jc++) {
            u32 b0 = *(const u32*)(brow + (16 * jc + 2 * q) * 2);
            u32 b1 = *(const u32*)(brow + (16 * jc + 2 * q + 8) * 2);
            MMA16816(d0, A[0][jc], b0, b1);
            MMA16816(d1, A[1][jc], b0, b1);
        }
        int k0 = n0 + 2 * q, k1 = k0 + 1;
        if (d0[0] > best[0]) { best[0] = d0[0]; bkk[0] = k0; }
        if (d0[1] > best[0]) { best[0] = d0[1]; bkk[0] = k1; }
        if (d0[2] > best[1]) { best[1] = d0[2]; bkk[1] = k0; }
        if (d0[3] > best[1]) { best[1] = d0[3]; bkk[1] = k1; }
        if (d1[0] > best[2]) { best[2] = d1[0]; bkk[2] = k0; }
        if (d1[1] > best[2]) { best[2] = d1[1]; bkk[2] = k1; }
        if (d1[2] > best[3]) { best[3] = d1[2]; bkk[3] = k0; }
        if (d1[3] > best[3]) { best[3] = d1[3]; bkk[3] = k1; }
    }

    #pragma unroll
    for (int r = 0; r < 4; r++) {
        #pragma unroll
        for (int o = 1; o <= 2; o <<= 1) {
            float ov = __shfl_xor_sync(0xFFFFFFFFu, best[r], o);
            int   ok = __shfl_xor_sync(0xFFFFFFFFu, bkk[r],  o);
            if (ov > best[r] || (ov == best[r] && ok < bkk[r])) { best[r] = ov; bkk[r] = ok; }
        }
    }
    if (q == 0) {
        sbk[wBase + g]      = bkk[0];
        sbk[wBase + g + 8]  = bkk[1];
        sbk[wBase + 16 + g] = bkk[2];
        sbk[wBase + 24 + g] = bkk[3];
    }
    __syncwarp();

    #pragma unroll 4
    for (int pl = 0; pl < 32; pl++) {
        int pt = wBase + pl;
        int bk = sbk[pt];
        float v0 = sxf[lane * PADF + pt];
        float v1 = sxf[(32 + lane) * PADF + pt];
        atomicAdd(g_sum + bk * HDIM + lane,      v0);
        atomicAdd(g_sum + bk * HDIM + 32 + lane, v1);
        if (lane == 0) atomicAdd(g_cnt + bk, 1.0f);
    }
}

// ---------------------------------------------------------------------------
// update3: closed-form 3-step EMA with frozen assignments; emit fp16 mn
// (out GEMM1 B) and fp16 transposed m (out GEMM2 B).
// ---------------------------------------------------------------------------
__global__ void update3_kernel() {
    int warp = threadIdx.x >> 5, lane = threadIdx.x & 31;
    int k = blockIdx.x * 8 + warp;
    if (k >= KDIM) return;
    const float R3  = RATE_F * RATE_F * RATE_F;
    const float IR3 = 1.0f - R3;
    float sc = IR3 / (g_cnt[k] + EPS_F);
    float m0 = g_m[k * HDIM + lane]      * R3 + g_sum[k * HDIM + lane]      * sc;
    float m1 = g_m[k * HDIM + 32 + lane] * R3 + g_sum[k * HDIM + 32 + lane] * sc;
    g_m[k * HDIM + lane]      = m0;
    g_m[k * HDIM + 32 + lane] = m1;
    float ssq = m0 * m0 + m1 * m1;
    #pragma unroll
    for (int o = 16; o; o >>= 1) ssq += __shfl_xor_sync(0xFFFFFFFFu, ssq, o);
    float inv = 1.0f / fmaxf(sqrtf(ssq), 1e-12f);
    g_mnh[k * HDIM + lane]      = __float2half(m0 * inv);
    g_mnh[k * HDIM + 32 + lane] = __float2half(m1 * inv);
    g_mTh[lane * KDIM + k]        = __float2half(m0);
    g_mTh[(32 + lane) * KDIM + k] = __float2half(m1);
}

// ---------------------------------------------------------------------------
// out via HMMA, 16 warps (512 thr), warp = 16 pts x 256 k:
//   GEMM1: S = Xscl(fp16) . MN(fp16)^T  (log2 domain)
//   e = ex2(S); den += e  (D-frag layout == GEMM2 A-frag layout)
//   GEMM2: N += (e_hi + e_lo) . mT_hi   (2-term; m_lo dropped ~2e-4)
//   out = N / den.
// k in 4 blocks of 64. smem 105 KB, 1 CTA/SM, regs capped at 128.
// ---------------------------------------------------------------------------
#define O_XH   0                       // [256 pt][72 h] = 36864
#define O_MN   36864                   // [256 k][144 B] = 36864
#define O_MTH  73728                   // [64 c][264 h]  = 33792
#define O_TOT  107520

__global__ void __launch_bounds__(512, 1) out_kernel(const float* __restrict__ x,
                                                     float* __restrict__ out) {
    extern __shared__ __align__(16) unsigned char smem[];
    __half* sxh = (__half*)(smem + O_XH);          // [pt][72h] rows 144B
    unsigned char* smn = smem + O_MN;              // [k][144B]
    __half* smtH = (__half*)(smem + O_MTH);        // [c][264h] rows 528B
    int tid = threadIdx.x;

    int hw0 = blockIdx.x * 256;
    int b   = hw0 >> 16;
    if (tid < 256) {
        // Warps 0-7: x. Pass 1 = norm; pass 2 = re-read (L2-hot) + fp16 cvt.
        const float* xb = x + (size_t)b * HDIM * HW + (hw0 & (HW - 1)) + tid;
        float s0 = 0.f, s1 = 0.f, s2 = 0.f, s3 = 0.f;
        #pragma unroll
        for (int c = 0; c < HDIM; c += 4) {
            float f0 = xb[(size_t)c * HW];
            float f1 = xb[(size_t)(c + 1) * HW];
            float f2 = xb[(size_t)(c + 2) * HW];
            float f3 = xb[(size_t)(c + 3) * HW];
            s0 = fmaf(f0, f0, s0); s1 = fmaf(f1, f1, s1);
            s2 = fmaf(f2, f2, s2); s3 = fmaf(f3, f3, s3);
        }
        float scl = 1.44269504088896f / fmaxf(sqrtf((s0 + s1) + (s2 + s3)), 1e-12f);
        __half* myrow = sxh + tid * 72;
        #pragma unroll
        for (int c = 0; c < HDIM; c++) myrow[c] = __float2half(xb[(size_t)c * HW] * scl);
    } else {
        int t2 = tid - 256;
        const uint4* src = (const uint4*)g_mnh;
        #pragma unroll 2
        for (int i = t2; i < KDIM * 8; i += 256) {
            int k = i >> 3, ch = i & 7;
            *(uint4*)(smn + k * 144 + ch * 16) = src[k * 8 + ch];
        }
        const uint4* sh = (const uint4*)g_mTh;
        #pragma unroll 2
        for (int i = t2; i < 64 * 32; i += 256) {
            int c = i >> 5, ch = i & 31;
            *(uint4*)((unsigned char*)smtH + c * 528 + ch * 16) = sh[i];
        }
    }
    __syncthreads();

    int w = tid >> 5, lane = tid & 31;
    int g = lane >> 2, q = lane & 3;
    int wBase = w * 16;

    // GEMM1 A fragments (x, fp16) — persistent, direct LDS (conflict-free).
    u32 A1[4][4];
    {
        const __half* r0 = sxh + (wBase + g) * 72;
        const __half* r1 = r0 + 8 * 72;
        #pragma unroll
        for (int jc = 0; jc < 4; jc++) {
            int c0 = 16 * jc + 2 * q;
            A1[jc][0] = *(const u32*)(r0 + c0);
            A1[jc][1] = *(const u32*)(r1 + c0);
            A1[jc][2] = *(const u32*)(r0 + c0 + 8);
            A1[jc][3] = *(const u32*)(r1 + c0 + 8);
        }
    }

    float acc[8][4];
    #pragma unroll
    for (int ct = 0; ct < 8; ct++)
        #pragma unroll
        for (int v = 0; v < 4; v++) acc[ct][v] = 0.0f;
    float den[2] = {0.f, 0.f};

    #pragma unroll
    for (int kb = 0; kb < 4; kb++) {
        // --- GEMM1: scores for this warp's 16 pts x 64 codes (log2 domain) ---
        float s[8][4];
        #pragma unroll
        for (int i = 0; i < 8; i++)
            #pragma unroll
            for (int v = 0; v < 4; v++) s[i][v] = 0.0f;
        #pragma unroll
        for (int i = 0; i < 8; i++) {
            const unsigned char* brow = smn + (kb * 64 + 8 * i + g) * 144;
            #pragma unroll
            for (int jc = 0; jc < 4; jc++) {
                u32 b0 = *(const u32*)(brow + (16 * jc + 2 * q) * 2);
                u32 b1 = *(const u32*)(brow + (16 * jc + 2 * q + 8) * 2);
                MMA16816(s[i], A1[jc], b0, b1);
            }
        }
        // --- e = 2^s; den accumulation (v<2: row g, v>=2: row g+8) ---
        #pragma unroll
        for (int i = 0; i < 8; i++) {
            #pragma unroll
            for (int v = 0; v < 4; v++) {
                float e = ex2f(s[i][v]);
                s[i][v] = e;
                den[v >> 1] += e;
            }
        }
        // --- e -> GEMM2 A fragments (hi/lo split; layout validated R16) ---
        u32 AH[4][4], AL[4][4];
        #pragma unroll
        for (int j = 0; j < 4; j++) {
            #pragma unroll
            for (int r = 0; r < 4; r++) {
                int i = 2 * j + (r >> 1);
                int v = (r & 1) * 2;
                float w0 = s[i][v], w1 = s[i][v + 1];
                u32 hi = h2(w1, w0);
                float2 hf = __half22float2(*(__half2*)&hi);
                AH[j][r] = hi;
                AL[j][r] = h2(w1 - hf.y, w0 - hf.x);
            }
        }
        // --- GEMM2: acc += (e_hi + e_lo) * mT_hi ---
        #pragma unroll
        for (int ct = 0; ct < 8; ct++) {
            const __half* rH = smtH + (8 * ct + g) * 264;
            #pragma unroll
            for (int j = 0; j < 4; j++) {
                int koff = kb * 64 + 16 * j + 2 * q;
                u32 b0h = *(const u32*)(rH + koff);
                u32 b1h = *(const u32*)(rH + koff + 8);
                MMA16816(acc[ct], AH[j], b0h, b1h);
                MMA16816(acc[ct], AL[j], b0h, b1h);
            }
        }
    }

    // den: sum across the 4 q-lanes sharing each row.
    #pragma unroll
    for (int r = 0; r < 2; r++) {
        den[r] += __shfl_xor_sync(0xFFFFFFFFu, den[r], 1);
        den[r] += __shfl_xor_sync(0xFFFFFFFFu, den[r], 2);
    }
    float iden0 = 1.0f / den[0];
    float iden1 = 1.0f / den[1];

    int hwb = hw0 & (HW - 1);
    float* ob = out + (size_t)b * HDIM * HW + hwb;
    int p0 = wBase + g;
    #pragma unroll
    for (int ct = 0; ct < 8; ct++) {
        int c = 8 * ct + 2 * q;
        ob[(size_t)c * HW + p0]           = acc[ct][0] * iden0;
        ob[(size_t)(c + 1) * HW + p0]     = acc[ct][1] * iden0;
        ob[(size_t)c * HW + p0 + 8]       = acc[ct][2] * iden1;
        ob[(size_t)(c + 1) * HW + p0 + 8] = acc[ct][3] * iden1;
    }
}

// ---------------------------------------------------------------------------
extern "C" void kernel_launch(void* const* d_in, const int* in_sizes, int n_in,
                              void* d_out, int out_size) {
    const float* x;
    const float* units;
    if (in_sizes[0] >= in_sizes[1]) { x = (const float*)d_in[0]; units = (const float*)d_in[1]; }
    else                            { x = (const float*)d_in[1]; units = (const float*)d_in[0]; }
    float* out = (float*)d_out;

    cudaFuncSetAttribute(assign_kernel, cudaFuncAttributeMaxDynamicSharedMemorySize, S_TOT);
    cudaFuncSetAttribute(out_kernel,    cudaFuncAttributeMaxDynamicSharedMemorySize, O_TOT);

    prep_kernel<<<32, 256>>>(units);
    assign_kernel<<<NPTS / 256, 256, S_TOT>>>(x);
    update3_kernel<<<32, 256>>>();
    out_kernel<<<NPTS / 256, 512, O_TOT>>>(x, out);
}